// round 1
// baseline (speedup 1.0000x reference)
#include <cuda_runtime.h>

#define TOK (8 * 64 * 64)   // 32768 tokens (b*h*w)
#define DIM 1024

// Scratch (allocation-free rule: __device__ globals)
__device__ float g_q[(size_t)TOK * DIM];
__device__ float g_k[(size_t)TOK * DIM];
__device__ float g_v[(size_t)TOK * DIM];
__device__ float g_attn[(size_t)TOK * DIM];

// ---------------------------------------------------------------------------
// C[m,n] = sum_k A[m,k] * W[n,k] + bias[n]      (TN GEMM, both K-contiguous)
// 128x128 tile, BK=8, 256 threads, 8x8 per-thread microtile.
// ---------------------------------------------------------------------------
__global__ __launch_bounds__(256, 2)
void sgemm_tn_bias(const float* __restrict__ A, const float* __restrict__ W,
                   const float* __restrict__ bias, float* __restrict__ C,
                   int M, int N, int K)
{
    __shared__ float As[8][128];
    __shared__ float Bs[8][128];

    const int tid = threadIdx.x;
    const int m0 = blockIdx.y * 128;
    const int n0 = blockIdx.x * 128;
    const int tx = tid & 15;        // 0..15  -> n microtile
    const int ty = tid >> 4;        // 0..15  -> m microtile
    const int lr = tid >> 1;        // 0..127 -> tile row loaded
    const int lc = (tid & 1) << 2;  // 0 or 4 -> k offset loaded

    const float* Ap = A + (size_t)(m0 + lr) * K + lc;
    const float* Wp = W + (size_t)(n0 + lr) * K + lc;

    float acc[8][8];
#pragma unroll
    for (int i = 0; i < 8; i++)
#pragma unroll
        for (int j = 0; j < 8; j++) acc[i][j] = 0.f;

    for (int k0 = 0; k0 < K; k0 += 8) {
        float4 av = *(const float4*)(Ap + k0);
        float4 bv = *(const float4*)(Wp + k0);
        __syncthreads();
        As[lc + 0][lr] = av.x; As[lc + 1][lr] = av.y;
        As[lc + 2][lr] = av.z; As[lc + 3][lr] = av.w;
        Bs[lc + 0][lr] = bv.x; Bs[lc + 1][lr] = bv.y;
        Bs[lc + 2][lr] = bv.z; Bs[lc + 3][lr] = bv.w;
        __syncthreads();
#pragma unroll
        for (int kk = 0; kk < 8; kk++) {
            float4 a0 = *(const float4*)&As[kk][ty * 8];
            float4 a1 = *(const float4*)&As[kk][ty * 8 + 4];
            float4 b0 = *(const float4*)&Bs[kk][tx * 8];
            float4 b1 = *(const float4*)&Bs[kk][tx * 8 + 4];
            float a[8] = {a0.x, a0.y, a0.z, a0.w, a1.x, a1.y, a1.z, a1.w};
            float b[8] = {b0.x, b0.y, b0.z, b0.w, b1.x, b1.y, b1.z, b1.w};
#pragma unroll
            for (int i = 0; i < 8; i++)
#pragma unroll
                for (int j = 0; j < 8; j++) acc[i][j] += a[i] * b[j];
        }
    }

#pragma unroll
    for (int i = 0; i < 8; i++) {
        const int m = m0 + ty * 8 + i;
#pragma unroll
        for (int j = 0; j < 8; j += 4) {
            const int n = n0 + tx * 8 + j;
            float4 o;
            o.x = acc[i][j + 0] + bias[n + 0];
            o.y = acc[i][j + 1] + bias[n + 1];
            o.z = acc[i][j + 2] + bias[n + 2];
            o.w = acc[i][j + 3] + bias[n + 3];
            *(float4*)&C[(size_t)m * N + n] = o;
        }
    }
}

// ---------------------------------------------------------------------------
// Axial attention: one CTA handles one 64-token axis slice.
//   row mode (col_mode=0): slice = (b,h), tokens index w, row stride = DIM
//   col mode (col_mode=1): slice = (b,w), tokens index h, row stride = W*DIM
// S[i][j] = q_i . k_j - gw*(i-j)^2 ; P = softmax_j(S) ; out_i = sum_j P[i][j] v_j
// Row kernel writes '='; col kernel accumulates '+='.
// ---------------------------------------------------------------------------
__global__ __launch_bounds__(256)
void axial_attn(const float* __restrict__ q, const float* __restrict__ k,
                const float* __restrict__ v, float* __restrict__ out,
                const float* __restrict__ sigma, int col_mode)
{
    // QT/KT hold a transposed 64(d) x 64(row) chunk (pad 68 keeps float4 align +
    // breaks store bank conflicts). S aliases KT (KT dead once S is written).
    __shared__ float QT[64][68];
    __shared__ float KT[64][68];
    float (*S)[65] = (float(*)[65]) & KT[0][0];   // 64*65 <= 64*68

    const int tid = threadIdx.x;
    const int bid = blockIdx.x;

    size_t base;
    int stride;
    if (col_mode) {
        const int b = bid >> 6, w = bid & 63;
        base = ((size_t)b * 64 * 64 + w) * DIM;
        stride = 64 * DIM;
    } else {
        base = (size_t)bid * 64 * DIM;
        stride = DIM;
    }

    const float sg = sigma[0];
    const float gw = 1.0f / (2.0f * sg * sg);

    const int i0 = (tid >> 4) << 2;   // 4*(tid/16): S row group
    const int j0 = (tid & 15) << 2;   // 4*(tid%16): S col group / d group

    float acc[4][4];
#pragma unroll
    for (int r = 0; r < 4; r++)
#pragma unroll
        for (int c = 0; c < 4; c++) acc[r][c] = 0.f;

    // ---- S = Q K^T, streamed over d in chunks of 64 ----
    for (int d0 = 0; d0 < DIM; d0 += 64) {
        __syncthreads();
#pragma unroll
        for (int it = 0; it < 4; it++) {
            const int idx = tid + it * 256;      // 0..1023
            const int row = idx >> 4;            // 0..63
            const int seg = (idx & 15) << 2;     // 0..60
            float4 qv = *(const float4*)(q + base + (size_t)row * stride + d0 + seg);
            float4 kv = *(const float4*)(k + base + (size_t)row * stride + d0 + seg);
            QT[seg + 0][row] = qv.x; QT[seg + 1][row] = qv.y;
            QT[seg + 2][row] = qv.z; QT[seg + 3][row] = qv.w;
            KT[seg + 0][row] = kv.x; KT[seg + 1][row] = kv.y;
            KT[seg + 2][row] = kv.z; KT[seg + 3][row] = kv.w;
        }
        __syncthreads();
#pragma unroll 8
        for (int kk = 0; kk < 64; kk++) {
            float4 a4 = *(const float4*)&QT[kk][i0];
            float4 b4 = *(const float4*)&KT[kk][j0];
            float a[4] = {a4.x, a4.y, a4.z, a4.w};
            float b[4] = {b4.x, b4.y, b4.z, b4.w};
#pragma unroll
            for (int r = 0; r < 4; r++)
#pragma unroll
                for (int c = 0; c < 4; c++) acc[r][c] += a[r] * b[c];
        }
    }

    __syncthreads();   // everyone done reading KT before S overwrites it
#pragma unroll
    for (int r = 0; r < 4; r++)
#pragma unroll
        for (int c = 0; c < 4; c++) {
            const float di = (float)((i0 + r) - (j0 + c));
            S[i0 + r][j0 + c] = acc[r][c] - gw * di * di;
        }
    __syncthreads();

    // ---- softmax over each row of S (4 threads per row) ----
    {
        const int row = tid >> 2;
        const int qb = (tid & 3) << 4;
        float mx = -1e30f;
#pragma unroll
        for (int c = 0; c < 16; c++) mx = fmaxf(mx, S[row][qb + c]);
        mx = fmaxf(mx, __shfl_xor_sync(0xffffffffu, mx, 1));
        mx = fmaxf(mx, __shfl_xor_sync(0xffffffffu, mx, 2));
        float sum = 0.f;
#pragma unroll
        for (int c = 0; c < 16; c++) {
            const float e = __expf(S[row][qb + c] - mx);
            S[row][qb + c] = e;
            sum += e;
        }
        sum += __shfl_xor_sync(0xffffffffu, sum, 1);
        sum += __shfl_xor_sync(0xffffffffu, sum, 2);
        const float inv = 1.0f / sum;
#pragma unroll
        for (int c = 0; c < 16; c++) S[row][qb + c] *= inv;
    }
    __syncthreads();

    // ---- out = P @ V, streamed over d in chunks of 64 (V reuses QT storage) ----
    for (int dc = 0; dc < DIM; dc += 64) {
        __syncthreads();
#pragma unroll
        for (int it = 0; it < 4; it++) {
            const int idx = tid + it * 256;
            const int row = idx >> 4;
            const int seg = (idx & 15) << 2;
            float4 vv = *(const float4*)(v + base + (size_t)row * stride + dc + seg);
            *(float4*)&QT[row][seg] = vv;     // row-major this time
        }
        __syncthreads();

        float o[4][4];
#pragma unroll
        for (int r = 0; r < 4; r++)
#pragma unroll
            for (int c = 0; c < 4; c++) o[r][c] = 0.f;

#pragma unroll 8
        for (int j = 0; j < 64; j++) {
            float p[4];
#pragma unroll
            for (int r = 0; r < 4; r++) p[r] = S[i0 + r][j];
            float4 v4 = *(const float4*)&QT[j][j0];
            float vb[4] = {v4.x, v4.y, v4.z, v4.w};
#pragma unroll
            for (int r = 0; r < 4; r++)
#pragma unroll
                for (int c = 0; c < 4; c++) o[r][c] += p[r] * vb[c];
        }

#pragma unroll
        for (int r = 0; r < 4; r++) {
            float* dst = out + base + (size_t)(i0 + r) * stride + dc + j0;
            float4 ov = {o[r][0], o[r][1], o[r][2], o[r][3]};
            if (col_mode) {
                float4 old = *(const float4*)dst;
                ov.x += old.x; ov.y += old.y; ov.z += old.z; ov.w += old.w;
            }
            *(float4*)dst = ov;
        }
    }
}

// ---------------------------------------------------------------------------
extern "C" void kernel_launch(void* const* d_in, const int* in_sizes, int n_in,
                              void* d_out, int out_size)
{
    const float* x     = (const float*)d_in[0];
    const float* Wq    = (const float*)d_in[1];
    const float* bq    = (const float*)d_in[2];
    const float* Wk    = (const float*)d_in[3];
    const float* bk    = (const float*)d_in[4];
    const float* Wv    = (const float*)d_in[5];
    const float* bv    = (const float*)d_in[6];
    const float* Wo    = (const float*)d_in[7];
    const float* bo    = (const float*)d_in[8];
    const float* sigma = (const float*)d_in[9];
    float* out = (float*)d_out;

    float *q, *k, *v, *attn;
    cudaGetSymbolAddress((void**)&q,    g_q);
    cudaGetSymbolAddress((void**)&k,    g_k);
    cudaGetSymbolAddress((void**)&v,    g_v);
    cudaGetSymbolAddress((void**)&attn, g_attn);

    const int M = TOK, N = DIM, K = DIM;
    dim3 gg(N / 128, M / 128);   // (8, 256)

    sgemm_tn_bias<<<gg, 256>>>(x, Wq, bq, q, M, N, K);
    sgemm_tn_bias<<<gg, 256>>>(x, Wk, bk, k, M, N, K);
    sgemm_tn_bias<<<gg, 256>>>(x, Wv, bv, v, M, N, K);

    axial_attn<<<512, 256>>>(q, k, v, attn, sigma, 0);   // rows: '='
    axial_attn<<<512, 256>>>(q, k, v, attn, sigma, 1);   // cols: '+='

    sgemm_tn_bias<<<gg, 256>>>(attn, Wo, bo, out, M, N, K);
}

// round 6
// speedup vs baseline: 1.3130x; 1.3130x over previous
#include <cuda_runtime.h>
#include <cuda_bf16.h>
#include <cstdint>

#define TOK (8 * 64 * 64)   // 32768 tokens
#define DIM 1024

// ---------------- scratch (allocation-free rule: __device__ globals) --------
__device__ float g_q[(size_t)TOK * DIM];
__device__ float g_k[(size_t)TOK * DIM];
__device__ float g_v[(size_t)TOK * DIM];
__device__ float g_attn[(size_t)TOK * DIM];
__device__ __nv_bfloat16 g_xh[(size_t)TOK * DIM];
__device__ __nv_bfloat16 g_xl[(size_t)TOK * DIM];
__device__ __nv_bfloat16 g_wh[(size_t)4 * DIM * DIM];
__device__ __nv_bfloat16 g_wl[(size_t)4 * DIM * DIM];

// ---------------- PTX helpers (non-'a' target safe) -------------------------
__device__ __forceinline__ uint32_t smem_u32(const void* p) {
    uint32_t a;
    asm("{ .reg .u64 t; cvta.to.shared.u64 t, %1; cvt.u32.u64 %0, t; }" : "=r"(a) : "l"(p));
    return a;
}
#define CP_ASYNC16(dst, src) \
    asm volatile("cp.async.cg.shared.global [%0], [%1], 16;" :: "r"(dst), "l"(src) : "memory")
#define CP_COMMIT() asm volatile("cp.async.commit_group;" ::: "memory")
#define CP_WAIT(n)  asm volatile("cp.async.wait_group %0;" :: "n"(n) : "memory")

__device__ __forceinline__ void ldm_x4(uint32_t* r, uint32_t addr) {
    asm volatile("ldmatrix.sync.aligned.m8n8.x4.shared.b16 {%0,%1,%2,%3}, [%4];"
                 : "=r"(r[0]), "=r"(r[1]), "=r"(r[2]), "=r"(r[3]) : "r"(addr));
}
__device__ __forceinline__ void ldm_x2(uint32_t* r, uint32_t addr) {
    asm volatile("ldmatrix.sync.aligned.m8n8.x2.shared.b16 {%0,%1}, [%2];"
                 : "=r"(r[0]), "=r"(r[1]) : "r"(addr));
}
__device__ __forceinline__ void mma_bf16(float* c, const uint32_t* a, const uint32_t* b) {
    asm volatile("mma.sync.aligned.m16n8k16.row.col.f32.bf16.bf16.f32 "
                 "{%0,%1,%2,%3}, {%4,%5,%6,%7}, {%8,%9}, {%0,%1,%2,%3};"
                 : "+f"(c[0]), "+f"(c[1]), "+f"(c[2]), "+f"(c[3])
                 : "r"(a[0]), "r"(a[1]), "r"(a[2]), "r"(a[3]), "r"(b[0]), "r"(b[1]));
}

// ---------------------------------------------------------------------------
// Split fp32 -> bf16 hi + bf16 lo
// ---------------------------------------------------------------------------
__global__ void split_kernel(const float* __restrict__ s, __nv_bfloat16* __restrict__ hi,
                             __nv_bfloat16* __restrict__ lo, int n4)
{
    int i = blockIdx.x * 256 + threadIdx.x;
    if (i >= n4) return;
    float4 x = ((const float4*)s)[i];
    __nv_bfloat162 h01, h23, l01, l23;
    h01.x = __float2bfloat16(x.x); h01.y = __float2bfloat16(x.y);
    h23.x = __float2bfloat16(x.z); h23.y = __float2bfloat16(x.w);
    l01.x = __float2bfloat16(x.x - __bfloat162float(h01.x));
    l01.y = __float2bfloat16(x.y - __bfloat162float(h01.y));
    l23.x = __float2bfloat16(x.z - __bfloat162float(h23.x));
    l23.y = __float2bfloat16(x.w - __bfloat162float(h23.y));
    ((__nv_bfloat162*)hi)[2 * i] = h01; ((__nv_bfloat162*)hi)[2 * i + 1] = h23;
    ((__nv_bfloat162*)lo)[2 * i] = l01; ((__nv_bfloat162*)lo)[2 * i + 1] = l23;
}

// ---------------------------------------------------------------------------
// Split-bf16 TN GEMM on mma.sync (HMMA): C[m,n] = sum_k A[m,k]*W[n,k] + bias[n]
// CTA 128x128, BK=32, 3-stage cp.async pipeline, 8 warps x (64x32 warp tile).
// Smem rows padded to 80B -> ldmatrix phases are bank-conflict-free.
// Per K-chunk: acc += Ah*Bh + Ah*Bl + Al*Bh  (fp32 accum).
// ---------------------------------------------------------------------------
#define ROWB 80                    // bytes per smem row (32 bf16 = 64B data + pad)
#define MATB (128 * ROWB)          // 10240 B per matrix tile
#define STAGEB (4 * MATB)          // Ah, Al, Bh, Bl
#define NSTAGE 3
#define NCHUNK 32                  // K / BK = 1024/32

__global__ __launch_bounds__(256)
void gemm_mma(const __nv_bfloat16* __restrict__ Ah, const __nv_bfloat16* __restrict__ Al,
              const __nv_bfloat16* __restrict__ Bh, const __nv_bfloat16* __restrict__ Bl,
              const float* __restrict__ bias, float* __restrict__ C)
{
    extern __shared__ char smem[];
    const uint32_t sb = smem_u32(smem);

    const int tid  = threadIdx.x;
    const int warp = tid >> 5;
    const int lane = tid & 31;
    const int m0   = blockIdx.y * 128;
    const int n0   = blockIdx.x * 128;
    const int wm   = warp & 1;          // 0..1 -> 64-row half
    const int wn   = warp >> 1;         // 0..3 -> 32-col quarter

    const __nv_bfloat16* gsrc[4] = { Ah + (size_t)m0 * DIM, Al + (size_t)m0 * DIM,
                                     Bh + (size_t)n0 * DIM, Bl + (size_t)n0 * DIM };

    // loader slots: per matrix 512 16B-chunks (128 rows x 4), 2 per thread
    auto load_chunk = [&](int stage, int chunk) {
        const uint32_t stb = sb + stage * STAGEB;
        const int k0 = chunk * 32;
#pragma unroll
        for (int mt = 0; mt < 4; mt++) {
            const __nv_bfloat16* src = gsrc[mt];
            const uint32_t mb = stb + mt * MATB;
#pragma unroll
            for (int t2 = 0; t2 < 2; t2++) {
                const int idx = t2 * 256 + tid;      // 0..511
                const int row = idx >> 2;            // 0..127
                const int c   = idx & 3;             // 16B chunk
                CP_ASYNC16(mb + row * ROWB + c * 16,
                           src + (size_t)row * DIM + k0 + c * 8);
            }
        }
    };

    load_chunk(0, 0); CP_COMMIT();
    load_chunk(1, 1); CP_COMMIT();

    float acc[4][4][4];
#pragma unroll
    for (int i = 0; i < 4; i++)
#pragma unroll
        for (int j = 0; j < 4; j++)
#pragma unroll
            for (int e = 0; e < 4; e++) acc[i][j][e] = 0.f;

    // ldmatrix address components (within a matrix tile)
    const int a_row = wm * 64 + (lane & 15);         // + mi*16
    const int a_sel = lane >> 4;                     // 0/1 -> k chunk within kstep
    const int b_row = wn * 32 + (lane & 7);          // + ni*8
    const int b_sel = (lane >> 3) & 1;

    for (int c = 0; c < NCHUNK; ++c) {
        if (c + 2 < NCHUNK) load_chunk((c + 2) % NSTAGE, c + 2);
        CP_COMMIT();
        CP_WAIT(2);
        __syncthreads();

        const uint32_t stb = sb + (c % NSTAGE) * STAGEB;
        const uint32_t bAh = stb;
        const uint32_t bAl = stb + MATB;
        const uint32_t bBh = stb + 2 * MATB;
        const uint32_t bBl = stb + 3 * MATB;

#pragma unroll
        for (int ks = 0; ks < 2; ks++) {
            const int kc = ks * 2;   // 16B chunk base of this kstep
            uint32_t ah[4][4], al[4][4], bh[4][2], bl[4][2];
#pragma unroll
            for (int mi = 0; mi < 4; mi++) {
                const uint32_t off = (uint32_t)(a_row + mi * 16) * ROWB + (kc + a_sel) * 16;
                ldm_x4(ah[mi], bAh + off);
                ldm_x4(al[mi], bAl + off);
            }
#pragma unroll
            for (int ni = 0; ni < 4; ni++) {
                const uint32_t off = (uint32_t)(b_row + ni * 8) * ROWB + (kc + b_sel) * 16;
                ldm_x2(bh[ni], bBh + off);
                ldm_x2(bl[ni], bBl + off);
            }
#pragma unroll
            for (int mi = 0; mi < 4; mi++)
#pragma unroll
                for (int ni = 0; ni < 4; ni++) {
                    mma_bf16(acc[mi][ni], ah[mi], bh[ni]);
                    mma_bf16(acc[mi][ni], ah[mi], bl[ni]);
                    mma_bf16(acc[mi][ni], al[mi], bh[ni]);
                }
        }
        __syncthreads();
    }

    // epilogue: bias + store (thread owns (g, 2t4) / (g+8, 2t4) per mma tile)
    const int g  = lane >> 2;
    const int t4 = lane & 3;
#pragma unroll
    for (int mi = 0; mi < 4; mi++) {
#pragma unroll
        for (int ni = 0; ni < 4; ni++) {
            const int n = n0 + wn * 32 + ni * 8 + t4 * 2;
            const float2 bv = *(const float2*)&bias[n];
            const int m_hi = m0 + wm * 64 + mi * 16 + g;
            float2 o0 = { acc[mi][ni][0] + bv.x, acc[mi][ni][1] + bv.y };
            float2 o1 = { acc[mi][ni][2] + bv.x, acc[mi][ni][3] + bv.y };
            *(float2*)&C[(size_t)m_hi * DIM + n]       = o0;
            *(float2*)&C[(size_t)(m_hi + 8) * DIM + n] = o1;
        }
    }
}

// ---------------------------------------------------------------------------
// Axial attention: one CTA per 64-token axis slice.
// ---------------------------------------------------------------------------
__global__ __launch_bounds__(256)
void axial_attn(const float* __restrict__ q, const float* __restrict__ k,
                const float* __restrict__ v, float* __restrict__ out,
                const float* __restrict__ sigma, int col_mode)
{
    __shared__ float QT[64][68];
    __shared__ float KT[64][68];
    float (*S)[65] = (float(*)[65]) & KT[0][0];

    const int tid = threadIdx.x;
    const int bid = blockIdx.x;

    size_t base;
    int stride;
    if (col_mode) {
        const int b = bid >> 6, w = bid & 63;
        base = ((size_t)b * 64 * 64 + w) * DIM;
        stride = 64 * DIM;
    } else {
        base = (size_t)bid * 64 * DIM;
        stride = DIM;
    }

    const float sg = sigma[0];
    const float gw = 1.0f / (2.0f * sg * sg);

    const int i0 = (tid >> 4) << 2;
    const int j0 = (tid & 15) << 2;

    float acc[4][4];
#pragma unroll
    for (int r = 0; r < 4; r++)
#pragma unroll
        for (int c = 0; c < 4; c++) acc[r][c] = 0.f;

    for (int d0 = 0; d0 < DIM; d0 += 64) {
        __syncthreads();
#pragma unroll
        for (int it = 0; it < 4; it++) {
            const int idx = tid + it * 256;
            const int row = idx >> 4;
            const int seg = (idx & 15) << 2;
            float4 qv = *(const float4*)(q + base + (size_t)row * stride + d0 + seg);
            float4 kv = *(const float4*)(k + base + (size_t)row * stride + d0 + seg);
            QT[seg + 0][row] = qv.x; QT[seg + 1][row] = qv.y;
            QT[seg + 2][row] = qv.z; QT[seg + 3][row] = qv.w;
            KT[seg + 0][row] = kv.x; KT[seg + 1][row] = kv.y;
            KT[seg + 2][row] = kv.z; KT[seg + 3][row] = kv.w;
        }
        __syncthreads();
#pragma unroll 8
        for (int kk = 0; kk < 64; kk++) {
            float4 a4 = *(const float4*)&QT[kk][i0];
            float4 b4 = *(const float4*)&KT[kk][j0];
            float a[4] = {a4.x, a4.y, a4.z, a4.w};
            float b[4] = {b4.x, b4.y, b4.z, b4.w};
#pragma unroll
            for (int r = 0; r < 4; r++)
#pragma unroll
                for (int c = 0; c < 4; c++) acc[r][c] += a[r] * b[c];
        }
    }

    __syncthreads();
#pragma unroll
    for (int r = 0; r < 4; r++)
#pragma unroll
        for (int c = 0; c < 4; c++) {
            const float di = (float)((i0 + r) - (j0 + c));
            S[i0 + r][j0 + c] = acc[r][c] - gw * di * di;
        }
    __syncthreads();

    {
        const int row = tid >> 2;
        const int qb = (tid & 3) << 4;
        float mx = -1e30f;
#pragma unroll
        for (int c = 0; c < 16; c++) mx = fmaxf(mx, S[row][qb + c]);
        mx = fmaxf(mx, __shfl_xor_sync(0xffffffffu, mx, 1));
        mx = fmaxf(mx, __shfl_xor_sync(0xffffffffu, mx, 2));
        float sum = 0.f;
#pragma unroll
        for (int c = 0; c < 16; c++) {
            const float e = __expf(S[row][qb + c] - mx);
            S[row][qb + c] = e;
            sum += e;
        }
        sum += __shfl_xor_sync(0xffffffffu, sum, 1);
        sum += __shfl_xor_sync(0xffffffffu, sum, 2);
        const float inv = 1.0f / sum;
#pragma unroll
        for (int c = 0; c < 16; c++) S[row][qb + c] *= inv;
    }
    __syncthreads();

    for (int dc = 0; dc < DIM; dc += 64) {
        __syncthreads();
#pragma unroll
        for (int it = 0; it < 4; it++) {
            const int idx = tid + it * 256;
            const int row = idx >> 4;
            const int seg = (idx & 15) << 2;
            float4 vv = *(const float4*)(v + base + (size_t)row * stride + dc + seg);
            *(float4*)&QT[row][seg] = vv;
        }
        __syncthreads();

        float o[4][4];
#pragma unroll
        for (int r = 0; r < 4; r++)
#pragma unroll
            for (int c = 0; c < 4; c++) o[r][c] = 0.f;

#pragma unroll 8
        for (int j = 0; j < 64; j++) {
            float p[4];
#pragma unroll
            for (int r = 0; r < 4; r++) p[r] = S[i0 + r][j];
            float4 v4 = *(const float4*)&QT[j][j0];
            float vb[4] = {v4.x, v4.y, v4.z, v4.w};
#pragma unroll
            for (int r = 0; r < 4; r++)
#pragma unroll
                for (int c = 0; c < 4; c++) o[r][c] += p[r] * vb[c];
        }

#pragma unroll
        for (int r = 0; r < 4; r++) {
            float* dst = out + base + (size_t)(i0 + r) * stride + dc + j0;
            float4 ov = {o[r][0], o[r][1], o[r][2], o[r][3]};
            if (col_mode) {
                float4 old = *(const float4*)dst;
                ov.x += old.x; ov.y += old.y; ov.z += old.z; ov.w += old.w;
            }
            *(float4*)dst = ov;
        }
    }
}

// ---------------------------------------------------------------------------
extern "C" void kernel_launch(void* const* d_in, const int* in_sizes, int n_in,
                              void* d_out, int out_size)
{
    const float* x     = (const float*)d_in[0];
    const float* Wq    = (const float*)d_in[1];
    const float* bq    = (const float*)d_in[2];
    const float* Wk    = (const float*)d_in[3];
    const float* bk    = (const float*)d_in[4];
    const float* Wv    = (const float*)d_in[5];
    const float* bv    = (const float*)d_in[6];
    const float* Wo    = (const float*)d_in[7];
    const float* bo    = (const float*)d_in[8];
    const float* sigma = (const float*)d_in[9];
    float* out = (float*)d_out;

    float *q, *k, *v, *attn;
    __nv_bfloat16 *xh, *xl, *wh, *wl;
    cudaGetSymbolAddress((void**)&q,    g_q);
    cudaGetSymbolAddress((void**)&k,    g_k);
    cudaGetSymbolAddress((void**)&v,    g_v);
    cudaGetSymbolAddress((void**)&attn, g_attn);
    cudaGetSymbolAddress((void**)&xh,   g_xh);
    cudaGetSymbolAddress((void**)&xl,   g_xl);
    cudaGetSymbolAddress((void**)&wh,   g_wh);
    cudaGetSymbolAddress((void**)&wl,   g_wl);

    const int SMEM_DYN = NSTAGE * STAGEB;   // 3 * 40960 = 122880 B
    cudaFuncSetAttribute(gemm_mma, cudaFuncAttributeMaxDynamicSharedMemorySize, SMEM_DYN);

    const size_t WSZ = (size_t)DIM * DIM;
    split_kernel<<<(TOK * DIM / 4) / 256, 256>>>(x, xh, xl, TOK * DIM / 4);
    split_kernel<<<(int)(WSZ / 4) / 256, 256>>>(Wq, wh + 0 * WSZ, wl + 0 * WSZ, (int)(WSZ / 4));
    split_kernel<<<(int)(WSZ / 4) / 256, 256>>>(Wk, wh + 1 * WSZ, wl + 1 * WSZ, (int)(WSZ / 4));
    split_kernel<<<(int)(WSZ / 4) / 256, 256>>>(Wv, wh + 2 * WSZ, wl + 2 * WSZ, (int)(WSZ / 4));
    split_kernel<<<(int)(WSZ / 4) / 256, 256>>>(Wo, wh + 3 * WSZ, wl + 3 * WSZ, (int)(WSZ / 4));

    dim3 gg(DIM / 128, TOK / 128);  // (8, 256)
    gemm_mma<<<gg, 256, SMEM_DYN>>>(xh, xl, wh + 0 * WSZ, wl + 0 * WSZ, bq, q);
    gemm_mma<<<gg, 256, SMEM_DYN>>>(xh, xl, wh + 1 * WSZ, wl + 1 * WSZ, bk, k);
    gemm_mma<<<gg, 256, SMEM_DYN>>>(xh, xl, wh + 2 * WSZ, wl + 2 * WSZ, bv, v);

    axial_attn<<<512, 256>>>(q, k, v, attn, sigma, 0);   // rows: '='
    axial_attn<<<512, 256>>>(q, k, v, attn, sigma, 1);   // cols: '+='

    split_kernel<<<(TOK * DIM / 4) / 256, 256>>>(attn, xh, xl, TOK * DIM / 4);
    gemm_mma<<<gg, 256, SMEM_DYN>>>(xh, xl, wh + 3 * WSZ, wl + 3 * WSZ, bo, out);
}

// round 9
// speedup vs baseline: 2.1247x; 1.6182x over previous
#include <cuda_runtime.h>
#include <cuda_bf16.h>
#include <cstdint>

#define TOK (8 * 64 * 64)   // 32768 tokens
#define DIM 1024

// ---------------- scratch (allocation-free rule: __device__ globals) --------
__device__ float g_q[(size_t)TOK * DIM];
__device__ float g_k[(size_t)TOK * DIM];
__device__ float g_v[(size_t)TOK * DIM];
__device__ float g_attn[(size_t)TOK * DIM];    // row-attention output
__device__ float g_attn2[(size_t)TOK * DIM];   // col-attention output
__device__ __nv_bfloat16 g_xh[(size_t)TOK * DIM];
__device__ __nv_bfloat16 g_xl[(size_t)TOK * DIM];
__device__ __nv_bfloat16 g_wh[(size_t)4 * DIM * DIM];
__device__ __nv_bfloat16 g_wl[(size_t)4 * DIM * DIM];

// ---------------- PTX helpers (non-'a' target safe) -------------------------
__device__ __forceinline__ uint32_t smem_u32(const void* p) {
    uint32_t a;
    asm("{ .reg .u64 t; cvta.to.shared.u64 t, %1; cvt.u32.u64 %0, t; }" : "=r"(a) : "l"(p));
    return a;
}
#define CP_ASYNC16(dst, src) \
    asm volatile("cp.async.cg.shared.global [%0], [%1], 16;" :: "r"(dst), "l"(src) : "memory")
#define CP_COMMIT() asm volatile("cp.async.commit_group;" ::: "memory")
#define CP_WAIT(n)  asm volatile("cp.async.wait_group %0;" :: "n"(n) : "memory")

__device__ __forceinline__ void ldm_x4(uint32_t* r, uint32_t addr) {
    asm volatile("ldmatrix.sync.aligned.m8n8.x4.shared.b16 {%0,%1,%2,%3}, [%4];"
                 : "=r"(r[0]), "=r"(r[1]), "=r"(r[2]), "=r"(r[3]) : "r"(addr));
}
__device__ __forceinline__ void ldm_x2(uint32_t* r, uint32_t addr) {
    asm volatile("ldmatrix.sync.aligned.m8n8.x2.shared.b16 {%0,%1}, [%2];"
                 : "=r"(r[0]), "=r"(r[1]) : "r"(addr));
}
__device__ __forceinline__ void mma_bf16(float* c, const uint32_t* a, const uint32_t* b) {
    asm volatile("mma.sync.aligned.m16n8k16.row.col.f32.bf16.bf16.f32 "
                 "{%0,%1,%2,%3}, {%4,%5,%6,%7}, {%8,%9}, {%0,%1,%2,%3};"
                 : "+f"(c[0]), "+f"(c[1]), "+f"(c[2]), "+f"(c[3])
                 : "r"(a[0]), "r"(a[1]), "r"(a[2]), "r"(a[3]), "r"(b[0]), "r"(b[1]));
}

// ---------------------------------------------------------------------------
// Split fp32 -> bf16 hi + bf16 lo
// ---------------------------------------------------------------------------
__device__ __forceinline__ void split4(float4 x, __nv_bfloat16* hi, __nv_bfloat16* lo, size_t i2)
{
    __nv_bfloat162 h01, h23, l01, l23;
    h01.x = __float2bfloat16(x.x); h01.y = __float2bfloat16(x.y);
    h23.x = __float2bfloat16(x.z); h23.y = __float2bfloat16(x.w);
    l01.x = __float2bfloat16(x.x - __bfloat162float(h01.x));
    l01.y = __float2bfloat16(x.y - __bfloat162float(h01.y));
    l23.x = __float2bfloat16(x.z - __bfloat162float(h23.x));
    l23.y = __float2bfloat16(x.w - __bfloat162float(h23.y));
    ((__nv_bfloat162*)hi)[i2] = h01; ((__nv_bfloat162*)hi)[i2 + 1] = h23;
    ((__nv_bfloat162*)lo)[i2] = l01; ((__nv_bfloat162*)lo)[i2 + 1] = l23;
}

__global__ void split_kernel(const float* __restrict__ s, __nv_bfloat16* __restrict__ hi,
                             __nv_bfloat16* __restrict__ lo, int n4)
{
    int i = blockIdx.x * 256 + threadIdx.x;
    if (i >= n4) return;
    split4(((const float4*)s)[i], hi, lo, 2 * (size_t)i);
}

// sum of two fp32 streams -> bf16 hi/lo split (fuses r_out + c_out)
__global__ void split_sum_kernel(const float* __restrict__ a, const float* __restrict__ b,
                                 __nv_bfloat16* __restrict__ hi, __nv_bfloat16* __restrict__ lo,
                                 int n4)
{
    int i = blockIdx.x * 256 + threadIdx.x;
    if (i >= n4) return;
    float4 xa = ((const float4*)a)[i];
    float4 xb = ((const float4*)b)[i];
    float4 x = { xa.x + xb.x, xa.y + xb.y, xa.z + xb.z, xa.w + xb.w };
    split4(x, hi, lo, 2 * (size_t)i);
}

// ---------------------------------------------------------------------------
// Split-bf16 TN GEMM on mma.sync (HMMA): C[m,n] = sum_k A[m,k]*W[n,k] + bias[n]
// CTA 128x128, BK=32, 4-stage cp.async pipeline, 8 warps x (64x32 warp tile).
// ---------------------------------------------------------------------------
#define ROWB 80                    // bytes per smem row (32 bf16 = 64B data + pad)
#define MATB (128 * ROWB)          // 10240 B per matrix tile
#define STAGEB (4 * MATB)          // Ah, Al, Bh, Bl
#define NSTAGE 4
#define NCHUNK 32                  // K / BK = 1024/32

__global__ __launch_bounds__(256)
void gemm_mma(const __nv_bfloat16* __restrict__ Ah, const __nv_bfloat16* __restrict__ Al,
              const __nv_bfloat16* __restrict__ Bh, const __nv_bfloat16* __restrict__ Bl,
              const float* __restrict__ bias, float* __restrict__ C)
{
    extern __shared__ char smem[];
    const uint32_t sb = smem_u32(smem);

    const int tid  = threadIdx.x;
    const int warp = tid >> 5;
    const int lane = tid & 31;
    const int m0   = blockIdx.y * 128;
    const int n0   = blockIdx.x * 128;
    const int wm   = warp & 1;          // 0..1 -> 64-row half
    const int wn   = warp >> 1;         // 0..3 -> 32-col quarter

    const __nv_bfloat16* gsrc[4] = { Ah + (size_t)m0 * DIM, Al + (size_t)m0 * DIM,
                                     Bh + (size_t)n0 * DIM, Bl + (size_t)n0 * DIM };

    auto load_chunk = [&](int stage, int chunk) {
        const uint32_t stb = sb + stage * STAGEB;
        const int k0 = chunk * 32;
#pragma unroll
        for (int mt = 0; mt < 4; mt++) {
            const __nv_bfloat16* src = gsrc[mt];
            const uint32_t mb = stb + mt * MATB;
#pragma unroll
            for (int t2 = 0; t2 < 2; t2++) {
                const int idx = t2 * 256 + tid;      // 0..511
                const int row = idx >> 2;            // 0..127
                const int c   = idx & 3;             // 16B chunk
                CP_ASYNC16(mb + row * ROWB + c * 16,
                           src + (size_t)row * DIM + k0 + c * 8);
            }
        }
    };

    load_chunk(0, 0); CP_COMMIT();
    load_chunk(1, 1); CP_COMMIT();
    load_chunk(2, 2); CP_COMMIT();

    float acc[4][4][4];
#pragma unroll
    for (int i = 0; i < 4; i++)
#pragma unroll
        for (int j = 0; j < 4; j++)
#pragma unroll
            for (int e = 0; e < 4; e++) acc[i][j][e] = 0.f;

    const int a_row = wm * 64 + (lane & 15);
    const int a_sel = lane >> 4;
    const int b_row = wn * 32 + (lane & 7);
    const int b_sel = (lane >> 3) & 1;

    for (int c = 0; c < NCHUNK; ++c) {
        if (c + 3 < NCHUNK) load_chunk((c + 3) % NSTAGE, c + 3);
        CP_COMMIT();
        CP_WAIT(3);
        __syncthreads();

        const uint32_t stb = sb + (c % NSTAGE) * STAGEB;
        const uint32_t bAh = stb;
        const uint32_t bAl = stb + MATB;
        const uint32_t bBh = stb + 2 * MATB;
        const uint32_t bBl = stb + 3 * MATB;

#pragma unroll
        for (int ks = 0; ks < 2; ks++) {
            const int kc = ks * 2;
            uint32_t ah[4][4], al[4][4], bh[4][2], bl[4][2];
#pragma unroll
            for (int mi = 0; mi < 4; mi++) {
                const uint32_t off = (uint32_t)(a_row + mi * 16) * ROWB + (kc + a_sel) * 16;
                ldm_x4(ah[mi], bAh + off);
                ldm_x4(al[mi], bAl + off);
            }
#pragma unroll
            for (int ni = 0; ni < 4; ni++) {
                const uint32_t off = (uint32_t)(b_row + ni * 8) * ROWB + (kc + b_sel) * 16;
                ldm_x2(bh[ni], bBh + off);
                ldm_x2(bl[ni], bBl + off);
            }
#pragma unroll
            for (int mi = 0; mi < 4; mi++)
#pragma unroll
                for (int ni = 0; ni < 4; ni++) {
                    mma_bf16(acc[mi][ni], ah[mi], bh[ni]);
                    mma_bf16(acc[mi][ni], ah[mi], bl[ni]);
                    mma_bf16(acc[mi][ni], al[mi], bh[ni]);
                }
        }
        __syncthreads();
    }

    const int g  = lane >> 2;
    const int t4 = lane & 3;
#pragma unroll
    for (int mi = 0; mi < 4; mi++) {
#pragma unroll
        for (int ni = 0; ni < 4; ni++) {
            const int n = n0 + wn * 32 + ni * 8 + t4 * 2;
            const float2 bv = *(const float2*)&bias[n];
            const int m_hi = m0 + wm * 64 + mi * 16 + g;
            float2 o0 = { acc[mi][ni][0] + bv.x, acc[mi][ni][1] + bv.y };
            float2 o1 = { acc[mi][ni][2] + bv.x, acc[mi][ni][3] + bv.y };
            *(float2*)&C[(size_t)m_hi * DIM + n]       = o0;
            *(float2*)&C[(size_t)(m_hi + 8) * DIM + n] = o1;
        }
    }
}

// ---------------------------------------------------------------------------
// Axial attention: one CTA per 64-token axis slice. bid<512: row slices ->
// out_r; bid>=512: col slices -> out_c (no RMW; summed in split_sum_kernel).
// ---------------------------------------------------------------------------
__global__ __launch_bounds__(256)
void axial_attn(const float* __restrict__ q, const float* __restrict__ k,
                const float* __restrict__ v, float* __restrict__ out_r,
                float* __restrict__ out_c, const float* __restrict__ sigma)
{
    __shared__ float QT[64][68];
    __shared__ float KT[64][68];
    float (*S)[65] = (float(*)[65]) & KT[0][0];

    const int tid = threadIdx.x;
    const int bid = blockIdx.x;
    const int col_mode = bid >> 9;           // 0: rows, 1: cols
    const int sid = bid & 511;

    size_t base;
    int stride;
    if (col_mode) {
        const int b = sid >> 6, w = sid & 63;
        base = ((size_t)b * 64 * 64 + w) * DIM;
        stride = 64 * DIM;
    } else {
        base = (size_t)sid * 64 * DIM;
        stride = DIM;
    }
    float* out = col_mode ? out_c : out_r;

    const float sg = sigma[0];
    const float gw = 1.0f / (2.0f * sg * sg);

    const int i0 = (tid >> 4) << 2;
    const int j0 = (tid & 15) << 2;

    float acc[4][4];
#pragma unroll
    for (int r = 0; r < 4; r++)
#pragma unroll
        for (int c = 0; c < 4; c++) acc[r][c] = 0.f;

    for (int d0 = 0; d0 < DIM; d0 += 64) {
        __syncthreads();
#pragma unroll
        for (int it = 0; it < 4; it++) {
            const int idx = tid + it * 256;
            const int row = idx >> 4;
            const int seg = (idx & 15) << 2;
            float4 qv = *(const float4*)(q + base + (size_t)row * stride + d0 + seg);
            float4 kv = *(const float4*)(k + base + (size_t)row * stride + d0 + seg);
            QT[seg + 0][row] = qv.x; QT[seg + 1][row] = qv.y;
            QT[seg + 2][row] = qv.z; QT[seg + 3][row] = qv.w;
            KT[seg + 0][row] = kv.x; KT[seg + 1][row] = kv.y;
            KT[seg + 2][row] = kv.z; KT[seg + 3][row] = kv.w;
        }
        __syncthreads();
#pragma unroll 8
        for (int kk = 0; kk < 64; kk++) {
            float4 a4 = *(const float4*)&QT[kk][i0];
            float4 b4 = *(const float4*)&KT[kk][j0];
            float a[4] = {a4.x, a4.y, a4.z, a4.w};
            float b[4] = {b4.x, b4.y, b4.z, b4.w};
#pragma unroll
            for (int r = 0; r < 4; r++)
#pragma unroll
                for (int c = 0; c < 4; c++) acc[r][c] += a[r] * b[c];
        }
    }

    __syncthreads();
#pragma unroll
    for (int r = 0; r < 4; r++)
#pragma unroll
        for (int c = 0; c < 4; c++) {
            const float di = (float)((i0 + r) - (j0 + c));
            S[i0 + r][j0 + c] = acc[r][c] - gw * di * di;
        }
    __syncthreads();

    {
        const int row = tid >> 2;
        const int qb = (tid & 3) << 4;
        float mx = -1e30f;
#pragma unroll
        for (int c = 0; c < 16; c++) mx = fmaxf(mx, S[row][qb + c]);
        mx = fmaxf(mx, __shfl_xor_sync(0xffffffffu, mx, 1));
        mx = fmaxf(mx, __shfl_xor_sync(0xffffffffu, mx, 2));
        float sum = 0.f;
#pragma unroll
        for (int c = 0; c < 16; c++) {
            const float e = __expf(S[row][qb + c] - mx);
            S[row][qb + c] = e;
            sum += e;
        }
        sum += __shfl_xor_sync(0xffffffffu, sum, 1);
        sum += __shfl_xor_sync(0xffffffffu, sum, 2);
        const float inv = 1.0f / sum;
#pragma unroll
        for (int c = 0; c < 16; c++) S[row][qb + c] *= inv;
    }
    __syncthreads();

    for (int dc = 0; dc < DIM; dc += 64) {
        __syncthreads();
#pragma unroll
        for (int it = 0; it < 4; it++) {
            const int idx = tid + it * 256;
            const int row = idx >> 4;
            const int seg = (idx & 15) << 2;
            float4 vv = *(const float4*)(v + base + (size_t)row * stride + dc + seg);
            *(float4*)&QT[row][seg] = vv;
        }
        __syncthreads();

        float o[4][4];
#pragma unroll
        for (int r = 0; r < 4; r++)
#pragma unroll
            for (int c = 0; c < 4; c++) o[r][c] = 0.f;

#pragma unroll 8
        for (int j = 0; j < 64; j++) {
            float p[4];
#pragma unroll
            for (int r = 0; r < 4; r++) p[r] = S[i0 + r][j];
            float4 v4 = *(const float4*)&QT[j][j0];
            float vb[4] = {v4.x, v4.y, v4.z, v4.w};
#pragma unroll
            for (int r = 0; r < 4; r++)
#pragma unroll
                for (int c = 0; c < 4; c++) o[r][c] += p[r] * vb[c];
        }

#pragma unroll
        for (int r = 0; r < 4; r++) {
            float* dst = out + base + (size_t)(i0 + r) * stride + dc + j0;
            float4 ov = {o[r][0], o[r][1], o[r][2], o[r][3]};
            *(float4*)dst = ov;
        }
    }
}

// ---------------------------------------------------------------------------
extern "C" void kernel_launch(void* const* d_in, const int* in_sizes, int n_in,
                              void* d_out, int out_size)
{
    const float* x     = (const float*)d_in[0];
    const float* Wq    = (const float*)d_in[1];
    const float* bq    = (const float*)d_in[2];
    const float* Wk    = (const float*)d_in[3];
    const float* bk    = (const float*)d_in[4];
    const float* Wv    = (const float*)d_in[5];
    const float* bv    = (const float*)d_in[6];
    const float* Wo    = (const float*)d_in[7];
    const float* bo    = (const float*)d_in[8];
    const float* sigma = (const float*)d_in[9];
    float* out = (float*)d_out;

    float *q, *k, *v, *attn, *attn2;
    __nv_bfloat16 *xh, *xl, *wh, *wl;
    cudaGetSymbolAddress((void**)&q,     g_q);
    cudaGetSymbolAddress((void**)&k,     g_k);
    cudaGetSymbolAddress((void**)&v,     g_v);
    cudaGetSymbolAddress((void**)&attn,  g_attn);
    cudaGetSymbolAddress((void**)&attn2, g_attn2);
    cudaGetSymbolAddress((void**)&xh,    g_xh);
    cudaGetSymbolAddress((void**)&xl,    g_xl);
    cudaGetSymbolAddress((void**)&wh,    g_wh);
    cudaGetSymbolAddress((void**)&wl,    g_wl);

    const int SMEM_DYN = NSTAGE * STAGEB;   // 4 * 40960 = 163840 B
    cudaFuncSetAttribute(gemm_mma, cudaFuncAttributeMaxDynamicSharedMemorySize, SMEM_DYN);

    const size_t WSZ = (size_t)DIM * DIM;
    const int WB = (int)(WSZ / 4) / 256;    // weight-split blocks
    dim3 gg(DIM / 128, TOK / 128);          // (8, 256)

    // interleaved: W just split is L2-hot for its GEMM; puts gemm_mma early for ncu
    split_kernel<<<(TOK * DIM / 4) / 256, 256>>>(x, xh, xl, TOK * DIM / 4);
    split_kernel<<<WB, 256>>>(Wq, wh + 0 * WSZ, wl + 0 * WSZ, (int)(WSZ / 4));
    gemm_mma<<<gg, 256, SMEM_DYN>>>(xh, xl, wh + 0 * WSZ, wl + 0 * WSZ, bq, q);
    split_kernel<<<WB, 256>>>(Wk, wh + 1 * WSZ, wl + 1 * WSZ, (int)(WSZ / 4));
    gemm_mma<<<gg, 256, SMEM_DYN>>>(xh, xl, wh + 1 * WSZ, wl + 1 * WSZ, bk, k);
    split_kernel<<<WB, 256>>>(Wv, wh + 2 * WSZ, wl + 2 * WSZ, (int)(WSZ / 4));
    gemm_mma<<<gg, 256, SMEM_DYN>>>(xh, xl, wh + 2 * WSZ, wl + 2 * WSZ, bv, v);
    split_kernel<<<WB, 256>>>(Wo, wh + 3 * WSZ, wl + 3 * WSZ, (int)(WSZ / 4));

    // row + col attention in one launch; col writes its own buffer (no RMW)
    axial_attn<<<1024, 256>>>(q, k, v, attn, attn2, sigma);

    // O projection: fused (attn + attn2) split, then GEMM into d_out
    split_sum_kernel<<<(TOK * DIM / 4) / 256, 256>>>(attn, attn2, xh, xl, TOK * DIM / 4);
    gemm_mma<<<gg, 256, SMEM_DYN>>>(xh, xl, wh + 3 * WSZ, wl + 3 * WSZ, bo, out);
}

// round 17
// speedup vs baseline: 2.3015x; 1.0832x over previous
#include <cuda_runtime.h>
#include <cuda_bf16.h>
#include <cstdint>

#define TOK (8 * 64 * 64)   // 32768 tokens
#define DIM 1024

// ---------------- scratch (allocation-free rule: __device__ globals) --------
__device__ float g_qkv[(size_t)3 * TOK * DIM];   // q | k | v contiguous
__device__ float g_attn[(size_t)TOK * DIM];      // row-attention output
__device__ float g_attn2[(size_t)TOK * DIM];     // col-attention output
__device__ __nv_bfloat16 g_xh[(size_t)TOK * DIM];
__device__ __nv_bfloat16 g_xl[(size_t)TOK * DIM];
__device__ __nv_bfloat16 g_wh[(size_t)4 * DIM * DIM];
__device__ __nv_bfloat16 g_wl[(size_t)4 * DIM * DIM];

struct Bias3 { const float* b[3]; };

// ---------------- PTX helpers (non-'a' target safe) -------------------------
__device__ __forceinline__ uint32_t smem_u32(const void* p) {
    uint32_t a;
    asm("{ .reg .u64 t; cvta.to.shared.u64 t, %1; cvt.u32.u64 %0, t; }" : "=r"(a) : "l"(p));
    return a;
}
#define CP_ASYNC16(dst, src) \
    asm volatile("cp.async.cg.shared.global [%0], [%1], 16;" :: "r"(dst), "l"(src) : "memory")
#define CP_COMMIT() asm volatile("cp.async.commit_group;" ::: "memory")
#define CP_WAIT(n)  asm volatile("cp.async.wait_group %0;" :: "n"(n) : "memory")

__device__ __forceinline__ void ldm_x4(uint32_t* r, uint32_t addr) {
    asm volatile("ldmatrix.sync.aligned.m8n8.x4.shared.b16 {%0,%1,%2,%3}, [%4];"
                 : "=r"(r[0]), "=r"(r[1]), "=r"(r[2]), "=r"(r[3]) : "r"(addr));
}
__device__ __forceinline__ void mma_bf16(float* c, const uint32_t* a, const uint32_t* b) {
    asm volatile("mma.sync.aligned.m16n8k16.row.col.f32.bf16.bf16.f32 "
                 "{%0,%1,%2,%3}, {%4,%5,%6,%7}, {%8,%9}, {%0,%1,%2,%3};"
                 : "+f"(c[0]), "+f"(c[1]), "+f"(c[2]), "+f"(c[3])
                 : "r"(a[0]), "r"(a[1]), "r"(a[2]), "r"(a[3]), "r"(b[0]), "r"(b[1]));
}

// ---------------------------------------------------------------------------
// Split fp32 -> bf16 hi + bf16 lo
// ---------------------------------------------------------------------------
__device__ __forceinline__ void split4(float4 x, __nv_bfloat16* hi, __nv_bfloat16* lo, size_t i2)
{
    __nv_bfloat162 h01, h23, l01, l23;
    h01.x = __float2bfloat16(x.x); h01.y = __float2bfloat16(x.y);
    h23.x = __float2bfloat16(x.z); h23.y = __float2bfloat16(x.w);
    l01.x = __float2bfloat16(x.x - __bfloat162float(h01.x));
    l01.y = __float2bfloat16(x.y - __bfloat162float(h01.y));
    l23.x = __float2bfloat16(x.z - __bfloat162float(h23.x));
    l23.y = __float2bfloat16(x.w - __bfloat162float(h23.y));
    ((__nv_bfloat162*)hi)[i2] = h01; ((__nv_bfloat162*)hi)[i2 + 1] = h23;
    ((__nv_bfloat162*)lo)[i2] = l01; ((__nv_bfloat162*)lo)[i2 + 1] = l23;
}

__global__ void split_kernel(const float* __restrict__ s, __nv_bfloat16* __restrict__ hi,
                             __nv_bfloat16* __restrict__ lo, int n4)
{
    int i = blockIdx.x * 256 + threadIdx.x;
    if (i >= n4) return;
    split4(((const float4*)s)[i], hi, lo, 2 * (size_t)i);
}

__global__ void split_sum_kernel(const float* __restrict__ a, const float* __restrict__ b,
                                 __nv_bfloat16* __restrict__ hi, __nv_bfloat16* __restrict__ lo,
                                 int n4)
{
    int i = blockIdx.x * 256 + threadIdx.x;
    if (i >= n4) return;
    float4 xa = ((const float4*)a)[i];
    float4 xb = ((const float4*)b)[i];
    float4 x = { xa.x + xb.x, xa.y + xb.y, xa.z + xb.z, xa.w + xb.w };
    split4(x, hi, lo, 2 * (size_t)i);
}

// ---------------------------------------------------------------------------
// Split-bf16 TN GEMM on mma.sync: C[m,n] = sum_k A[m,k]*W[n,k] + bias[n]
// CTA 128x128, BK=32, 5-stage cp.async pipeline, ONE barrier per chunk.
// grid.x = 8*nsel: sel = blockIdx.x>>3 picks weight third / bias / output third.
// ---------------------------------------------------------------------------
#define ROWB 80                    // bytes per smem row (32 bf16 = 64B + pad)
#define MATB (128 * ROWB)          // 10240 B per matrix tile
#define STAGEB (4 * MATB)          // Ah, Al, Bh, Bl
#define NSTAGE 5
#define NCHUNK 32                  // K / BK

__global__ __launch_bounds__(256)
void gemm_mma(const __nv_bfloat16* __restrict__ Ah, const __nv_bfloat16* __restrict__ Al,
              const __nv_bfloat16* __restrict__ Bh, const __nv_bfloat16* __restrict__ Bl,
              Bias3 bias3, float* __restrict__ C)
{
    extern __shared__ char smem[];
    const uint32_t sb = smem_u32(smem);

    const int tid  = threadIdx.x;
    const int warp = tid >> 5;
    const int lane = tid & 31;
    const int sel  = blockIdx.x >> 3;
    const int m0   = blockIdx.y * 128;
    const int n0   = (blockIdx.x & 7) * 128;
    const int wm   = warp & 1;
    const int wn   = warp >> 1;

    const size_t WSZ = (size_t)DIM * DIM;
    const float* bias = bias3.b[sel];
    C  += (size_t)sel * TOK * DIM;

    const __nv_bfloat16* gsrc[4] = { Ah + (size_t)m0 * DIM, Al + (size_t)m0 * DIM,
                                     Bh + sel * WSZ + (size_t)n0 * DIM,
                                     Bl + sel * WSZ + (size_t)n0 * DIM };

    auto load_chunk = [&](int stage, int chunk) {
        const uint32_t stb = sb + stage * STAGEB;
        const int k0 = chunk * 32;
#pragma unroll
        for (int mt = 0; mt < 4; mt++) {
            const __nv_bfloat16* src = gsrc[mt];
            const uint32_t mb = stb + mt * MATB;
#pragma unroll
            for (int t2 = 0; t2 < 2; t2++) {
                const int idx = t2 * 256 + tid;      // 0..511
                const int row = idx >> 2;
                const int c   = idx & 3;
                CP_ASYNC16(mb + row * ROWB + c * 16,
                           src + (size_t)row * DIM + k0 + c * 8);
            }
        }
    };

    load_chunk(0, 0); CP_COMMIT();
    load_chunk(1, 1); CP_COMMIT();
    load_chunk(2, 2); CP_COMMIT();

    float acc[4][4][4];
#pragma unroll
    for (int i = 0; i < 4; i++)
#pragma unroll
        for (int j = 0; j < 4; j++)
#pragma unroll
            for (int e = 0; e < 4; e++) acc[i][j][e] = 0.f;

    // A fragment addressing (x4: 16 rows x 2 k-halves)
    const int a_row = wm * 64 + (lane & 15);
    const int a_sel = lane >> 4;
    // B fragment addressing (x4 covers 2 n-tiles x 2 k-halves):
    // lanes 0-7: rows+0 @kc | 8-15: rows+0 @kc+1 | 16-23: rows+8 @kc | 24-31: rows+8 @kc+1
    const int b4_row = wn * 32 + ((lane >> 4) << 3) + (lane & 7);
    const int b4_sel = (lane >> 3) & 1;

    for (int c = 0; c < NCHUNK; ++c) {
        if (c + 3 < NCHUNK) load_chunk((c + 3) % NSTAGE, c + 3);
        CP_COMMIT();
        CP_WAIT(3);
        __syncthreads();                      // single barrier per chunk

        const uint32_t stb = sb + (c % NSTAGE) * STAGEB;
        const uint32_t bAh = stb;
        const uint32_t bAl = stb + MATB;
        const uint32_t bBh = stb + 2 * MATB;
        const uint32_t bBl = stb + 3 * MATB;

#pragma unroll
        for (int ks = 0; ks < 2; ks++) {
            const int kc = ks * 2;
            uint32_t ah[4][4], al[4][4], bh[4][2], bl[4][2];
#pragma unroll
            for (int mi = 0; mi < 4; mi++) {
                const uint32_t off = (uint32_t)(a_row + mi * 16) * ROWB + (kc + a_sel) * 16;
                ldm_x4(ah[mi], bAh + off);
                ldm_x4(al[mi], bAl + off);
            }
#pragma unroll
            for (int ni2 = 0; ni2 < 2; ni2++) {
                const uint32_t off = (uint32_t)(b4_row + ni2 * 16) * ROWB + (kc + b4_sel) * 16;
                uint32_t rh[4], rl[4];
                ldm_x4(rh, bBh + off);
                ldm_x4(rl, bBl + off);
                bh[ni2 * 2][0] = rh[0]; bh[ni2 * 2][1] = rh[1];
                bh[ni2 * 2 + 1][0] = rh[2]; bh[ni2 * 2 + 1][1] = rh[3];
                bl[ni2 * 2][0] = rl[0]; bl[ni2 * 2][1] = rl[1];
                bl[ni2 * 2 + 1][0] = rl[2]; bl[ni2 * 2 + 1][1] = rl[3];
            }
#pragma unroll
            for (int mi = 0; mi < 4; mi++)
#pragma unroll
                for (int ni = 0; ni < 4; ni++) {
                    mma_bf16(acc[mi][ni], ah[mi], bh[ni]);
                    mma_bf16(acc[mi][ni], ah[mi], bl[ni]);
                    mma_bf16(acc[mi][ni], al[mi], bh[ni]);
                }
        }
        // no trailing barrier: stage reuse distance (5) + top barrier protect it
    }

    const int g  = lane >> 2;
    const int t4 = lane & 3;
#pragma unroll
    for (int mi = 0; mi < 4; mi++) {
#pragma unroll
        for (int ni = 0; ni < 4; ni++) {
            const int n = n0 + wn * 32 + ni * 8 + t4 * 2;
            const float2 bv = *(const float2*)&bias[n];
            const int m_hi = m0 + wm * 64 + mi * 16 + g;
            float2 o0 = { acc[mi][ni][0] + bv.x, acc[mi][ni][1] + bv.y };
            float2 o1 = { acc[mi][ni][2] + bv.x, acc[mi][ni][3] + bv.y };
            *(float2*)&C[(size_t)m_hi * DIM + n]       = o0;
            *(float2*)&C[(size_t)(m_hi + 8) * DIM + n] = o1;
        }
    }
}

// ---------------------------------------------------------------------------
// Axial attention: one CTA per 64-token axis slice. bid<512: rows -> out_r;
// bid>=512: cols -> out_c (no RMW; summed in split_sum_kernel).
// ---------------------------------------------------------------------------
__global__ __launch_bounds__(256)
void axial_attn(const float* __restrict__ q, const float* __restrict__ k,
                const float* __restrict__ v, float* __restrict__ out_r,
                float* __restrict__ out_c, const float* __restrict__ sigma)
{
    __shared__ float QT[64][68];
    __shared__ float KT[64][68];
    float (*S)[65] = (float(*)[65]) & KT[0][0];

    const int tid = threadIdx.x;
    const int bid = blockIdx.x;
    const int col_mode = bid >> 9;
    const int sid = bid & 511;

    size_t base;
    int stride;
    if (col_mode) {
        const int b = sid >> 6, w = sid & 63;
        base = ((size_t)b * 64 * 64 + w) * DIM;
        stride = 64 * DIM;
    } else {
        base = (size_t)sid * 64 * DIM;
        stride = DIM;
    }
    float* out = col_mode ? out_c : out_r;

    const float sg = sigma[0];
    const float gw = 1.0f / (2.0f * sg * sg);

    const int i0 = (tid >> 4) << 2;
    const int j0 = (tid & 15) << 2;

    float acc[4][4];
#pragma unroll
    for (int r = 0; r < 4; r++)
#pragma unroll
        for (int c = 0; c < 4; c++) acc[r][c] = 0.f;

    for (int d0 = 0; d0 < DIM; d0 += 64) {
        __syncthreads();
#pragma unroll
        for (int it = 0; it < 4; it++) {
            const int idx = tid + it * 256;
            const int row = idx >> 4;
            const int seg = (idx & 15) << 2;
            float4 qv = *(const float4*)(q + base + (size_t)row * stride + d0 + seg);
            float4 kv = *(const float4*)(k + base + (size_t)row * stride + d0 + seg);
            QT[seg + 0][row] = qv.x; QT[seg + 1][row] = qv.y;
            QT[seg + 2][row] = qv.z; QT[seg + 3][row] = qv.w;
            KT[seg + 0][row] = kv.x; KT[seg + 1][row] = kv.y;
            KT[seg + 2][row] = kv.z; KT[seg + 3][row] = kv.w;
        }
        __syncthreads();
#pragma unroll 8
        for (int kk = 0; kk < 64; kk++) {
            float4 a4 = *(const float4*)&QT[kk][i0];
            float4 b4 = *(const float4*)&KT[kk][j0];
            float a[4] = {a4.x, a4.y, a4.z, a4.w};
            float b[4] = {b4.x, b4.y, b4.z, b4.w};
#pragma unroll
            for (int r = 0; r < 4; r++)
#pragma unroll
                for (int c = 0; c < 4; c++) acc[r][c] += a[r] * b[c];
        }
    }

    __syncthreads();
#pragma unroll
    for (int r = 0; r < 4; r++)
#pragma unroll
        for (int c = 0; c < 4; c++) {
            const float di = (float)((i0 + r) - (j0 + c));
            S[i0 + r][j0 + c] = acc[r][c] - gw * di * di;
        }
    __syncthreads();

    {
        const int row = tid >> 2;
        const int qb = (tid & 3) << 4;
        float mx = -1e30f;
#pragma unroll
        for (int c = 0; c < 16; c++) mx = fmaxf(mx, S[row][qb + c]);
        mx = fmaxf(mx, __shfl_xor_sync(0xffffffffu, mx, 1));
        mx = fmaxf(mx, __shfl_xor_sync(0xffffffffu, mx, 2));
        float sum = 0.f;
#pragma unroll
        for (int c = 0; c < 16; c++) {
            const float e = __expf(S[row][qb + c] - mx);
            S[row][qb + c] = e;
            sum += e;
        }
        sum += __shfl_xor_sync(0xffffffffu, sum, 1);
        sum += __shfl_xor_sync(0xffffffffu, sum, 2);
        const float inv = 1.0f / sum;
#pragma unroll
        for (int c = 0; c < 16; c++) S[row][qb + c] *= inv;
    }
    __syncthreads();

    for (int dc = 0; dc < DIM; dc += 64) {
        __syncthreads();
#pragma unroll
        for (int it = 0; it < 4; it++) {
            const int idx = tid + it * 256;
            const int row = idx >> 4;
            const int seg = (idx & 15) << 2;
            float4 vv = *(const float4*)(v + base + (size_t)row * stride + dc + seg);
            *(float4*)&QT[row][seg] = vv;
        }
        __syncthreads();

        float o[4][4];
#pragma unroll
        for (int r = 0; r < 4; r++)
#pragma unroll
            for (int c = 0; c < 4; c++) o[r][c] = 0.f;

#pragma unroll 8
        for (int j = 0; j < 64; j++) {
            float p[4];
#pragma unroll
            for (int r = 0; r < 4; r++) p[r] = S[i0 + r][j];
            float4 v4 = *(const float4*)&QT[j][j0];
            float vb[4] = {v4.x, v4.y, v4.z, v4.w};
#pragma unroll
            for (int r = 0; r < 4; r++)
#pragma unroll
                for (int c = 0; c < 4; c++) o[r][c] += p[r] * vb[c];
        }

#pragma unroll
        for (int r = 0; r < 4; r++) {
            float* dst = out + base + (size_t)(i0 + r) * stride + dc + j0;
            float4 ov = {o[r][0], o[r][1], o[r][2], o[r][3]};
            *(float4*)dst = ov;
        }
    }
}

// ---------------------------------------------------------------------------
extern "C" void kernel_launch(void* const* d_in, const int* in_sizes, int n_in,
                              void* d_out, int out_size)
{
    const float* x     = (const float*)d_in[0];
    const float* Wq    = (const float*)d_in[1];
    const float* bq    = (const float*)d_in[2];
    const float* Wk    = (const float*)d_in[3];
    const float* bk    = (const float*)d_in[4];
    const float* Wv    = (const float*)d_in[5];
    const float* bv    = (const float*)d_in[6];
    const float* Wo    = (const float*)d_in[7];
    const float* bo    = (const float*)d_in[8];
    const float* sigma = (const float*)d_in[9];
    float* out = (float*)d_out;

    float *qkv, *attn, *attn2;
    __nv_bfloat16 *xh, *xl, *wh, *wl;
    cudaGetSymbolAddress((void**)&qkv,   g_qkv);
    cudaGetSymbolAddress((void**)&attn,  g_attn);
    cudaGetSymbolAddress((void**)&attn2, g_attn2);
    cudaGetSymbolAddress((void**)&xh,    g_xh);
    cudaGetSymbolAddress((void**)&xl,    g_xl);
    cudaGetSymbolAddress((void**)&wh,    g_wh);
    cudaGetSymbolAddress((void**)&wl,    g_wl);

    const int SMEM_DYN = NSTAGE * STAGEB;   // 5 * 40960 = 204800 B
    cudaFuncSetAttribute(gemm_mma, cudaFuncAttributeMaxDynamicSharedMemorySize, SMEM_DYN);

    const size_t WSZ = (size_t)DIM * DIM;
    const int WB = (int)(WSZ / 4) / 256;

    // launches 0-4: splits; launch 5: fused QKV GEMM (ncu -s 5 -c 1 captures it)
    split_kernel<<<(TOK * DIM / 4) / 256, 256>>>(x, xh, xl, TOK * DIM / 4);
    split_kernel<<<WB, 256>>>(Wq, wh + 0 * WSZ, wl + 0 * WSZ, (int)(WSZ / 4));
    split_kernel<<<WB, 256>>>(Wk, wh + 1 * WSZ, wl + 1 * WSZ, (int)(WSZ / 4));
    split_kernel<<<WB, 256>>>(Wv, wh + 2 * WSZ, wl + 2 * WSZ, (int)(WSZ / 4));
    split_kernel<<<WB, 256>>>(Wo, wh + 3 * WSZ, wl + 3 * WSZ, (int)(WSZ / 4));

    Bias3 bqkv = { { bq, bk, bv } };
    dim3 gqkv(24, TOK / 128);               // sel = x>>3 picks Q/K/V
    gemm_mma<<<gqkv, 256, SMEM_DYN>>>(xh, xl, wh, wl, bqkv, qkv);

    const float* q = qkv;
    const float* k = qkv + (size_t)TOK * DIM;
    const float* v = qkv + (size_t)2 * TOK * DIM;
    axial_attn<<<1024, 256>>>(q, k, v, attn, attn2, sigma);

    split_sum_kernel<<<(TOK * DIM / 4) / 256, 256>>>(attn, attn2, xh, xl, TOK * DIM / 4);

    Bias3 bout = { { bo, bo, bo } };
    dim3 go(8, TOK / 128);                  // sel = 0 always
    gemm_mma<<<go, 256, SMEM_DYN>>>(xh, xl, wh + 3 * WSZ, wl + 3 * WSZ, bout, out);
}